// round 10
// baseline (speedup 1.0000x reference)
#include <cuda_runtime.h>
#include <cstdint>

#define NB   8
#define CIN  64
#define HH   128
#define WW   128
#define LL   (HH*WW)      /* 16384 */
#define KK   576
#define COUT 128
#define TOFF 4096         /* keys ~N(0,42); 4096 = 98 sigma */
#define TSIZE 8200
#define SENT 0x7FFFFFFF

#define BM     16         /* reps per conv tile */
#define NKC    4          /* split-k chunks */
#define KCH    (KK/NKC)   /* 144 */
#define MAXREP 8192

#define CCH  8            /* summ: channels per smem chunk */
#define SROW 136          /* summ: padded smem row stride (floats) */

// ---- packed f32x2 helpers (sm_103a FFMA2 is PTX-only) ----
#define FMA_F32X2(d, a, b, c) \
    asm("fma.rn.f32x2 %0, %1, %2, %3;" : "=l"(d) : "l"(a), "l"(b), "l"(c))
#define PACK2(out, lo, hi) \
    asm("mov.b64 %0, {%1, %2};" : "=l"(out) : "f"(lo), "f"(hi))
#define UNPACK2(lo, hi, in) \
    asm("mov.b64 {%0, %1}, %2;" : "=f"(lo), "=f"(hi) : "l"(in))

__device__ __forceinline__ uint32_t smem_u32(const void* p) {
    uint32_t a;
    asm("{ .reg .u64 t; cvta.to.shared.u64 t, %1; cvt.u32.u64 %0, t; }"
        : "=r"(a) : "l"(p));
    return a;
}

// ---------------- scratch (static device globals) ----------------
__device__ int   d_table[NB*TSIZE];
__device__ int   d_summ [NB*LL];
__device__ int   d_ridx [NB*LL];
__device__ int   d_list [NB*LL];
__device__ int   d_count;
__device__ float d_wt4  [KK*COUT];
__device__ float d_tmp2 [(size_t)NB*LL*COUT];

// ---------------- 1a. init table + counter ----------------
__global__ void init_k() {
    int i = blockIdx.x*blockDim.x + threadIdx.x;
    if (i < NB*TSIZE) d_table[i] = SENT;
    if (i == 0) d_count = 0;
}

// ---------------- 1b. zero conv accumulator region ----------------
__global__ void zero_k() {
    int i = blockIdx.x*blockDim.x + threadIdx.x;
    float4 z = {0.f, 0.f, 0.f, 0.f};
    if (i < MAXREP*COUT/4)
        reinterpret_cast<float4*>(d_tmp2)[i] = z;
}

// ---------------- 1c. weight relayout: [k/4][o][4] ----------------
__global__ void wt_k(const float* __restrict__ weight) {
    int i = blockIdx.x*blockDim.x + threadIdx.x;
    if (i >= KK*COUT) return;
    int k = i >> 7;
    int o = i & 127;
    d_wt4[(k >> 2)*(COUT*4) + o*4 + (k & 3)] = weight[o*KK + k];
}

// ---------------- 2. summ (register-pipelined smem staging) --------------
// R9 version verbatim. Per-accumulator add ORDER identical to the verified
// reference order (c asc, di asc, then w-1, w, w+1). Bit-exact keys.
// DO NOT reassociate. (Launch #4 -> profiled this round.)
__global__ void __launch_bounds__(256)
summ_k(const float* __restrict__ fmap) {
    __shared__ float sm[CCH*4*SROW];   /* 17408 B */

    int bi = blockIdx.x;
    int n  = bi >> 6;
    int h0 = (bi & 63) << 1;
    int tid  = threadIdx.x;
    int w    = tid & 127;
    int hloc = tid >> 7;

    if (tid < CCH*4) {
        sm[tid*SROW + 3]   = 0.f;
        sm[tid*SROW + 132] = 0.f;
    }

    const float* gp[4];
    float*       sp[4];
    bool         gv[4];
    #pragma unroll
    for (int j = 0; j < 4; j++) {
        int idx = tid + j*256;
        int c   = idx >> 7;
        int r   = (idx >> 5) & 3;
        int w4  = idx & 31;
        int hr  = h0 - 1 + r;
        gv[j] = (hr >= 0 && hr < HH);
        gp[j] = fmap + (size_t)n*CIN*LL + (size_t)c*LL + (gv[j] ? hr : 0)*WW + (w4 << 2);
        sp[j] = sm + (c*4 + r)*SROW + 4 + (w4 << 2);
    }

    float4 rg[4];
    const float4 z4 = {0.f, 0.f, 0.f, 0.f};
    #pragma unroll
    for (int j = 0; j < 4; j++)
        rg[j] = gv[j] ? *reinterpret_cast<const float4*>(gp[j]) : z4;

    float a = 0.f;

    for (int c0 = 0; c0 < CIN; c0 += CCH) {
        __syncthreads();
        #pragma unroll
        for (int j = 0; j < 4; j++)
            *reinterpret_cast<float4*>(sp[j]) = rg[j];
        __syncthreads();

        if (c0 + CCH < CIN) {
            #pragma unroll
            for (int j = 0; j < 4; j++)
                rg[j] = gv[j] ? *reinterpret_cast<const float4*>(gp[j] + (size_t)(c0 + CCH)*LL) : z4;
        }

        #pragma unroll
        for (int c = 0; c < CCH; c++) {
            #pragma unroll
            for (int di = 0; di < 3; di++) {
                const float* row = sm + (c*4 + hloc + di)*SROW + w;
                a += row[3];
                a += row[4];
                a += row[5];
            }
        }
    }

    int h  = h0 + hloc;
    int l  = h*WW + w;
    float mean = a / 576.0f;
    float s    = mean * 1000.0f;
    int iv = (int)s;
    iv = max(-TOFF, min(TOFF-1, iv));
    d_summ[n*LL + l] = iv;
    atomicMin(&d_table[n*TSIZE + iv + TOFF], l);
}

// ---------------- 3. compact reps, assign dense rep ids ----------------
__global__ void rep_k() {
    int t = blockIdx.x*blockDim.x + threadIdx.x;
    if (t >= NB*LL) return;
    int n = t >> 14;
    int l = t & (LL-1);
    int v = d_summ[t];
    if (d_table[n*TSIZE + v + TOFF] == l) {
        int idx = atomicAdd(&d_count, 1);
        d_list[idx] = t;
        d_ridx[t]   = idx;
    }
}

// ---------------- 4. conv: cp.async double-buffered split-k GEMM ---------
// Stage tile t+1 via zfill cp.async while computing tile t. f32x2 compute
// loop identical to the verified R9 version. Patch layout [el][rr].
__device__ __forceinline__ void stage_tile(const float* __restrict__ fmap,
                                           int tile, int nrep, float* dst) {
    int kc = tile & (NKC-1);
    int rb = tile >> 2;
    int r0 = rb*BM;
    int cnt = min(BM, nrep - r0);
    int kbase = kc*KCH;
    uint32_t sbase = smem_u32(dst);
    #pragma unroll
    for (int j = 0; j < 9; j++) {               /* KCH*BM = 2304 = 9*256 */
        int i  = threadIdx.x + j*256;
        int el = i >> 4;
        int rr = i & 15;
        const float* src = fmap;                /* valid dummy when zfill */
        int size = 0;
        if (rr < cnt) {
            int e  = kbase + el;
            int t  = d_list[r0 + rr];
            int n  = t >> 14;
            int l  = t & (LL-1);
            int h  = l >> 7;
            int w  = l & 127;
            int c  = e / 9;
            int k9 = e - c*9;
            int di = k9 / 3;
            int dj = k9 - di*3;
            int hr = h + di - 1;
            int wc = w + dj - 1;
            if (hr >= 0 && hr < HH && wc >= 0 && wc < WW) {
                src = fmap + ((size_t)(n*CIN + c))*LL + hr*WW + wc;
                size = 4;
            }
        }
        asm volatile("cp.async.ca.shared.global [%0], [%1], 4, %2;"
                     :: "r"(sbase + i*4), "l"(src), "r"(size) : "memory");
    }
}

__global__ void __launch_bounds__(256)
conv5_k(const float* __restrict__ fmap) {
    __shared__ float patch[2][KCH*BM];          /* 2 x 9216 B */

    int o   = threadIdx.x & 127;
    int rg2 = threadIdx.x >> 7;
    int nrep = d_count;
    int nrb  = (nrep + BM - 1) / BM;
    int ntile = nrb * NKC;

    int t = blockIdx.x;
    if (t < ntile) stage_tile(fmap, t, nrep, patch[0]);
    asm volatile("cp.async.commit_group;" ::: "memory");

    for (int it = 0; t < ntile; t += gridDim.x, it++) {
        int cur = it & 1;
        asm volatile("cp.async.wait_group 0;" ::: "memory");
        __syncthreads();                        /* data visible + prev compute done */

        int nxt = t + gridDim.x;
        if (nxt < ntile) stage_tile(fmap, nxt, nrep, patch[cur ^ 1]);
        asm volatile("cp.async.commit_group;" ::: "memory");

        /* ---- compute tile t from patch[cur] (verified R9 loop) ---- */
        int kc = t & (NKC-1);
        int rb = t >> 2;
        int r0 = rb*BM;
        int kbase = kc*KCH;

        uint64_t acc2[4];
        #pragma unroll
        for (int j = 0; j < 4; j++) acc2[j] = 0ull;

        uint32_t sbase = smem_u32(patch[cur]) + (rg2*8)*4;
        const float* wb = d_wt4 + (kbase >> 2)*(COUT*4) + o*4;

        #pragma unroll 2
        for (int k0 = 0; k0 < KCH; k0 += 4) {
            float4 wv = *reinterpret_cast<const float4*>(wb + (k0 >> 2)*(COUT*4));
            float wk[4] = {wv.x, wv.y, wv.z, wv.w};
            #pragma unroll
            for (int kk = 0; kk < 4; kk++) {
                uint64_t w2;
                PACK2(w2, wk[kk], wk[kk]);
                uint32_t sa = sbase + ((k0 + kk)*BM)*4;
                uint64_t p01, p23, p45, p67;
                asm("ld.shared.v2.u64 {%0, %1}, [%2];"
                    : "=l"(p01), "=l"(p23) : "r"(sa));
                asm("ld.shared.v2.u64 {%0, %1}, [%2];"
                    : "=l"(p45), "=l"(p67) : "r"(sa + 16));
                FMA_F32X2(acc2[0], w2, p01, acc2[0]);
                FMA_F32X2(acc2[1], w2, p23, acc2[1]);
                FMA_F32X2(acc2[2], w2, p45, acc2[2]);
                FMA_F32X2(acc2[3], w2, p67, acc2[3]);
            }
        }

        #pragma unroll
        for (int j = 0; j < 4; j++) {
            float lo, hi;
            UNPACK2(lo, hi, acc2[j]);
            int rid = r0 + rg2*8 + 2*j;
            if (rid < nrep)
                atomicAdd(&d_tmp2[(size_t)rid*COUT + o], lo);
            if (rid + 1 < nrep)
                atomicAdd(&d_tmp2[(size_t)(rid + 1)*COUT + o], hi);
        }
        /* no trailing sync: next iter's wait+sync protects patch reuse */
    }
}

// ---------------- 5. gather (rep lookup + smem transpose + bias) ---------
__global__ void gather_t(const float* __restrict__ bias, float* __restrict__ out) {
    __shared__ float sm[32*129];
    __shared__ int   rids[32];

    int n  = blockIdx.x >> 9;
    int lt = blockIdx.x & 511;
    int l0 = lt << 5;
    int tid = threadIdx.x;

    if (tid < 32) {
        int v = d_summ[(n << 14) + l0 + tid];
        int r = d_table[n*TSIZE + v + TOFF];
        rids[tid] = d_ridx[(n << 14) + r];
    }
    __syncthreads();

    #pragma unroll
    for (int j = 0; j < 4; j++) {
        int idx = tid + j*256;
        int row = idx >> 5;
        int o4  = (idx & 31) << 2;
        float4 v = *reinterpret_cast<const float4*>(
            d_tmp2 + (size_t)rids[row]*COUT + o4);
        float4 b = *reinterpret_cast<const float4*>(bias + o4);
        sm[row*129 + o4 + 0] = v.x + b.x;
        sm[row*129 + o4 + 1] = v.y + b.y;
        sm[row*129 + o4 + 2] = v.z + b.z;
        sm[row*129 + o4 + 3] = v.w + b.w;
    }
    __syncthreads();

    #pragma unroll
    for (int j = 0; j < 4; j++) {
        int idx = tid + j*256;
        int o   = idx >> 3;
        int l4  = (idx & 7) << 2;
        float4 v;
        v.x = sm[(l4 + 0)*129 + o];
        v.y = sm[(l4 + 1)*129 + o];
        v.z = sm[(l4 + 2)*129 + o];
        v.w = sm[(l4 + 3)*129 + o];
        *reinterpret_cast<float4*>(
            out + (((size_t)n*COUT + o) << 14) + l0 + l4) = v;
    }
}

// ---------------- launch ----------------
extern "C" void kernel_launch(void* const* d_in, const int* in_sizes, int n_in,
                              void* d_out, int out_size) {
    const float* fmap   = (const float*)d_in[0];
    const float* weight = (const float*)d_in[1];
    const float* bias   = (const float*)d_in[2];
    float* out = (float*)d_out;

    init_k  <<<(NB*TSIZE + 255)/256, 256>>>();            /* #1 */
    zero_k  <<<(MAXREP*COUT/4 + 255)/256, 256>>>();       /* #2 */
    wt_k    <<<(KK*COUT + 255)/256, 256>>>(weight);       /* #3 */
    summ_k  <<<NB*64, 256>>>(fmap);                       /* #4 <- profiled */
    rep_k   <<<(NB*LL + 255)/256, 256>>>();               /* #5 */
    conv5_k <<<296, 256>>>(fmap);                         /* #6 */
    gather_t<<<NB*512, 256>>>(bias, out);                 /* #7 */
}

// round 11
// speedup vs baseline: 1.1274x; 1.1274x over previous
#include <cuda_runtime.h>
#include <cstdint>

#define NB   8
#define CIN  64
#define HH   128
#define WW   128
#define LL   (HH*WW)      /* 16384 */
#define KK   576
#define COUT 128
#define TOFF 4096         /* keys ~N(0,42); 4096 = 98 sigma */
#define TSIZE 8200
#define SENT 0x7FFFFFFF

#define BM     16         /* reps per conv tile */
#define NKC    4          /* split-k chunks */
#define KCH    (KK/NKC)   /* 144 */
#define TEL    (KCH*BM)   /* 2304 elements per tile */
#define MAXREP 8192

#define CCH  8            /* summ: channels per smem chunk */
#define SROW 136          /* summ: padded smem row stride (floats) */

// ---- packed f32x2 helpers (sm_103a FFMA2 is PTX-only) ----
#define FMA_F32X2(d, a, b, c) \
    asm("fma.rn.f32x2 %0, %1, %2, %3;" : "=l"(d) : "l"(a), "l"(b), "l"(c))
#define PACK2(out, lo, hi) \
    asm("mov.b64 %0, {%1, %2};" : "=l"(out) : "f"(lo), "f"(hi))
#define UNPACK2(lo, hi, in) \
    asm("mov.b64 {%0, %1}, %2;" : "=f"(lo), "=f"(hi) : "l"(in))

__device__ __forceinline__ uint32_t smem_u32(const void* p) {
    uint32_t a;
    asm("{ .reg .u64 t; cvta.to.shared.u64 t, %1; cvt.u32.u64 %0, t; }"
        : "=r"(a) : "l"(p));
    return a;
}

// ---------------- scratch (static device globals) ----------------
__device__ int   d_table[NB*TSIZE];
__device__ int   d_summ [NB*LL];
__device__ int   d_ridx [NB*LL];
__device__ int   d_list [NB*LL];
__device__ int   d_count;
__device__ float d_wt4  [KK*COUT];
__device__ float d_tmp2 [(size_t)NB*LL*COUT];

// ---------------- 1. setup: table init + tmp2 zero + weight relayout -----
__global__ void setup_k(const float* __restrict__ weight) {
    int i = blockIdx.x*blockDim.x + threadIdx.x;
    if (i == 0) d_count = 0;
    if (i < NB*TSIZE) d_table[i] = SENT;
    if (i < KK*COUT) {
        int k = i >> 7;
        int o = i & 127;
        d_wt4[(k >> 2)*(COUT*4) + o*4 + (k & 3)] = weight[o*KK + k];
    }
    if (i < MAXREP*COUT/4) {
        float4 z = {0.f, 0.f, 0.f, 0.f};
        reinterpret_cast<float4*>(d_tmp2)[i] = z;
    }
}

// ---------------- 2. summ (register-pipelined smem staging) --------------
// R9 version verbatim (21.3us measured, ~19us LDS floor). Per-accumulator
// add ORDER identical to the verified reference order (c asc, di asc, then
// w-1, w, w+1). Bit-exact keys. DO NOT reassociate.
__global__ void __launch_bounds__(256)
summ_k(const float* __restrict__ fmap) {
    __shared__ float sm[CCH*4*SROW];   /* 17408 B */

    int bi = blockIdx.x;
    int n  = bi >> 6;
    int h0 = (bi & 63) << 1;
    int tid  = threadIdx.x;
    int w    = tid & 127;
    int hloc = tid >> 7;

    if (tid < CCH*4) {
        sm[tid*SROW + 3]   = 0.f;
        sm[tid*SROW + 132] = 0.f;
    }

    const float* gp[4];
    float*       sp[4];
    bool         gv[4];
    #pragma unroll
    for (int j = 0; j < 4; j++) {
        int idx = tid + j*256;
        int c   = idx >> 7;
        int r   = (idx >> 5) & 3;
        int w4  = idx & 31;
        int hr  = h0 - 1 + r;
        gv[j] = (hr >= 0 && hr < HH);
        gp[j] = fmap + (size_t)n*CIN*LL + (size_t)c*LL + (gv[j] ? hr : 0)*WW + (w4 << 2);
        sp[j] = sm + (c*4 + r)*SROW + 4 + (w4 << 2);
    }

    float4 rg[4];
    const float4 z4 = {0.f, 0.f, 0.f, 0.f};
    #pragma unroll
    for (int j = 0; j < 4; j++)
        rg[j] = gv[j] ? *reinterpret_cast<const float4*>(gp[j]) : z4;

    float a = 0.f;

    for (int c0 = 0; c0 < CIN; c0 += CCH) {
        __syncthreads();
        #pragma unroll
        for (int j = 0; j < 4; j++)
            *reinterpret_cast<float4*>(sp[j]) = rg[j];
        __syncthreads();

        if (c0 + CCH < CIN) {
            #pragma unroll
            for (int j = 0; j < 4; j++)
                rg[j] = gv[j] ? *reinterpret_cast<const float4*>(gp[j] + (size_t)(c0 + CCH)*LL) : z4;
        }

        #pragma unroll
        for (int c = 0; c < CCH; c++) {
            #pragma unroll
            for (int di = 0; di < 3; di++) {
                const float* row = sm + (c*4 + hloc + di)*SROW + w;
                a += row[3];
                a += row[4];
                a += row[5];
            }
        }
    }

    int h  = h0 + hloc;
    int l  = h*WW + w;
    float mean = a / 576.0f;
    float s    = mean * 1000.0f;
    int iv = (int)s;
    iv = max(-TOFF, min(TOFF-1, iv));
    d_summ[n*LL + l] = iv;
    atomicMin(&d_table[n*TSIZE + iv + TOFF], l);
}

// ---------------- 3. compact reps, assign dense rep ids ----------------
__global__ void rep_k() {
    int t = blockIdx.x*blockDim.x + threadIdx.x;
    if (t >= NB*LL) return;
    int n = t >> 14;
    int l = t & (LL-1);
    int v = d_summ[t];
    if (d_table[n*TSIZE + v + TOFF] == l) {
        int idx = atomicAdd(&d_count, 1);
        d_list[idx] = t;
        d_ridx[t]   = idx;
    }
}

// ---------------- 4. conv: register-pipelined split-k GEMM ---------------
// 512 threads = 128 o x 4 rep-groups of 4. Grid 296 (2 blocks/SM, ~2 tiles
// per block): tile t+1 staged into registers WHILE tile t computes (summ's
// proven pattern). f32x2 accumulate; atomics combine split-k parts.
__device__ __forceinline__ void ld_tile(const float* __restrict__ fmap,
                                        int tile, int nrep, float st[5]) {
    int kc = tile & (NKC-1);
    int rb = tile >> 2;
    int r0 = rb*BM;
    int cnt = min(BM, nrep - r0);
    int kbase = kc*KCH;
    #pragma unroll
    for (int j = 0; j < 5; j++) {
        int i = threadIdx.x + j*512;
        float v = 0.f;
        if (i < TEL) {
            int el = i >> 4;
            int rr = i & 15;
            if (rr < cnt) {
                int e  = kbase + el;
                int t  = d_list[r0 + rr];
                int n  = t >> 14;
                int l  = t & (LL-1);
                int h  = l >> 7;
                int w  = l & 127;
                int c  = e / 9;
                int k9 = e - c*9;
                int di = k9 / 3;
                int dj = k9 - di*3;
                int hr = h + di - 1;
                int wc = w + dj - 1;
                if (hr >= 0 && hr < HH && wc >= 0 && wc < WW)
                    v = fmap[((size_t)(n*CIN + c))*LL + hr*WW + wc];
            }
        }
        st[j] = v;
    }
}

__global__ void __launch_bounds__(512)
conv6_k(const float* __restrict__ fmap) {
    __shared__ float patch[TEL];      /* [el][rr], 9216 B */

    int o   = threadIdx.x & 127;
    int rg4 = threadIdx.x >> 7;       /* 0..3 -> reps rg4*4 .. rg4*4+3 */
    int nrep = d_count;
    int nrb  = (nrep + BM - 1) / BM;
    int ntile = nrb * NKC;

    int t = blockIdx.x;
    float st[5];
    if (t < ntile) ld_tile(fmap, t, nrep, st);

    for (; t < ntile; t += gridDim.x) {
        __syncthreads();              /* prev compute done */
        #pragma unroll
        for (int j = 0; j < 5; j++) {
            int i = threadIdx.x + j*512;
            if (i < TEL) patch[i] = st[j];
        }
        __syncthreads();

        int nxt = t + gridDim.x;
        if (nxt < ntile) ld_tile(fmap, nxt, nrep, st);  /* overlap with compute */

        int kc = t & (NKC-1);
        int rb = t >> 2;
        int r0 = rb*BM;
        int kbase = kc*KCH;

        uint64_t acc2[2];             /* pairs (4j,4j+1),(4j+2,4j+3) of group */
        acc2[0] = 0ull; acc2[1] = 0ull;

        uint32_t sbase = smem_u32(patch) + rg4*16;     /* 4 reps = 16B */
        const float* wb = d_wt4 + (kbase >> 2)*(COUT*4) + o*4;

        #pragma unroll 4
        for (int k0 = 0; k0 < KCH; k0 += 4) {
            float4 wv = *reinterpret_cast<const float4*>(wb + (k0 >> 2)*(COUT*4));
            float wk[4] = {wv.x, wv.y, wv.z, wv.w};
            #pragma unroll
            for (int kk = 0; kk < 4; kk++) {
                uint64_t w2;
                PACK2(w2, wk[kk], wk[kk]);
                uint64_t p01, p23;
                asm("ld.shared.v2.u64 {%0, %1}, [%2];"
                    : "=l"(p01), "=l"(p23)
                    : "r"(sbase + ((k0 + kk)*BM)*4));  /* 16B broadcast */
                FMA_F32X2(acc2[0], w2, p01, acc2[0]);
                FMA_F32X2(acc2[1], w2, p23, acc2[1]);
            }
        }

        #pragma unroll
        for (int j = 0; j < 2; j++) {
            float lo, hi;
            UNPACK2(lo, hi, acc2[j]);
            int rid = r0 + rg4*4 + 2*j;
            if (rid < nrep)
                atomicAdd(&d_tmp2[(size_t)rid*COUT + o], lo);
            if (rid + 1 < nrep)
                atomicAdd(&d_tmp2[(size_t)(rid + 1)*COUT + o], hi);
        }
    }
}

// ---------------- 5. gather (rep lookup + smem transpose + bias) ---------
__global__ void gather_t(const float* __restrict__ bias, float* __restrict__ out) {
    __shared__ float sm[32*129];
    __shared__ int   rids[32];

    int n  = blockIdx.x >> 9;
    int lt = blockIdx.x & 511;
    int l0 = lt << 5;
    int tid = threadIdx.x;

    if (tid < 32) {
        int v = d_summ[(n << 14) + l0 + tid];
        int r = d_table[n*TSIZE + v + TOFF];
        rids[tid] = d_ridx[(n << 14) + r];
    }
    __syncthreads();

    #pragma unroll
    for (int j = 0; j < 4; j++) {
        int idx = tid + j*256;
        int row = idx >> 5;
        int o4  = (idx & 31) << 2;
        float4 v = *reinterpret_cast<const float4*>(
            d_tmp2 + (size_t)rids[row]*COUT + o4);
        float4 b = *reinterpret_cast<const float4*>(bias + o4);
        sm[row*129 + o4 + 0] = v.x + b.x;
        sm[row*129 + o4 + 1] = v.y + b.y;
        sm[row*129 + o4 + 2] = v.z + b.z;
        sm[row*129 + o4 + 3] = v.w + b.w;
    }
    __syncthreads();

    #pragma unroll
    for (int j = 0; j < 4; j++) {
        int idx = tid + j*256;
        int o   = idx >> 3;
        int l4  = (idx & 7) << 2;
        float4 v;
        v.x = sm[(l4 + 0)*129 + o];
        v.y = sm[(l4 + 1)*129 + o];
        v.z = sm[(l4 + 2)*129 + o];
        v.w = sm[(l4 + 3)*129 + o];
        *reinterpret_cast<float4*>(
            out + (((size_t)n*COUT + o) << 14) + l0 + l4) = v;
    }
}

// ---------------- launch ----------------
extern "C" void kernel_launch(void* const* d_in, const int* in_sizes, int n_in,
                              void* d_out, int out_size) {
    const float* fmap   = (const float*)d_in[0];
    const float* weight = (const float*)d_in[1];
    const float* bias   = (const float*)d_in[2];
    float* out = (float*)d_out;

    setup_k <<<(MAXREP*COUT/4 + 255)/256, 256>>>(weight); /* #1 */
    summ_k  <<<NB*64, 256>>>(fmap);                       /* #2 */
    rep_k   <<<(NB*LL + 255)/256, 256>>>();               /* #3 */
    conv6_k <<<296, 512>>>(fmap);                         /* #4 <- profiled */
    gather_t<<<NB*512, 256>>>(bias, out);                 /* #5 */
}